// round 1
// baseline (speedup 1.0000x reference)
#include <cuda_runtime.h>

#define REL_CONTEXT 0.2f

#define BM 128
#define BN 128
#define BK 16

__device__ float g_zeta;

// zeta = sigmoid(REL_CONTEXT * sum(Wrc) + brc)
__global__ void zeta_kernel(const float* __restrict__ Wrc,
                            const float* __restrict__ brc, int D) {
    __shared__ float red[32];
    float s = 0.f;
    for (int i = threadIdx.x; i < D; i += blockDim.x) s += Wrc[i];
    #pragma unroll
    for (int o = 16; o > 0; o >>= 1) s += __shfl_down_sync(0xffffffffu, s, o);
    if ((threadIdx.x & 31) == 0) red[threadIdx.x >> 5] = s;
    __syncthreads();
    if (threadIdx.x < 32) {
        int nw = blockDim.x >> 5;
        float v = (threadIdx.x < nw) ? red[threadIdx.x] : 0.f;
        #pragma unroll
        for (int o = 16; o > 0; o >>= 1) v += __shfl_down_sync(0xffffffffu, v, o);
        if (threadIdx.x == 0) {
            float z = REL_CONTEXT * v + brc[0];
            g_zeta = 1.f / (1.f + expf(-z));
        }
    }
}

// out[n, e] = relu( mw[n % M] * zeta * relu( sum_d (x[n,d] + emb[id[n],d]) * Wt[e,d] + bt[e] ) )
__global__ __launch_bounds__(256, 2)
void redaf_gemm(const float* __restrict__ x,
                const int*   __restrict__ ids,
                const float* __restrict__ mw,
                const float* __restrict__ emb,
                const float* __restrict__ Wt,
                const float* __restrict__ bt,
                float*       __restrict__ out,
                int Nrows, int D, int M)
{
    __shared__ float As[BK][BM];
    __shared__ float Bs[BK][BN];

    const int tid     = threadIdx.x;
    const int rowBase = blockIdx.y * BM;
    const int colBase = blockIdx.x * BN;

    // ---- global-load mapping: each thread stages one row's 8 consecutive k's ----
    const int ldRow = tid >> 1;          // 0..127
    const int ldK   = (tid & 1) * 8;     // 0 or 8

    const int aRow = rowBase + ldRow;
    const int bRow = colBase + ldRow;    // 'e' index into Wt
    const int myId = ids[aRow];
    const float* aPtr = x   + (size_t)aRow * D;
    const float* ePtr = emb + (size_t)myId * D;
    const float* bPtr = Wt  + (size_t)bRow * D;

    // ---- compute mapping: 16x16 threads, 8x8 micro-tile split (4 + 4 @ +64) ----
    const int ty = tid >> 4;             // 0..15
    const int tx = tid & 15;             // 0..15

    float acc[8][8];
    #pragma unroll
    for (int i = 0; i < 8; i++)
        #pragma unroll
        for (int j = 0; j < 8; j++) acc[i][j] = 0.f;

    // ---- initial staged fetch (A = x + emb fused at load) ----
    float4 ra0, ra1, rb0, rb1;
    {
        float4 x0 = *(const float4*)(aPtr + ldK);
        float4 x1 = *(const float4*)(aPtr + ldK + 4);
        float4 e0 = *(const float4*)(ePtr + ldK);
        float4 e1 = *(const float4*)(ePtr + ldK + 4);
        ra0 = make_float4(x0.x + e0.x, x0.y + e0.y, x0.z + e0.z, x0.w + e0.w);
        ra1 = make_float4(x1.x + e1.x, x1.y + e1.y, x1.z + e1.z, x1.w + e1.w);
        rb0 = *(const float4*)(bPtr + ldK);
        rb1 = *(const float4*)(bPtr + ldK + 4);
    }

    for (int kt = 0; kt < D; kt += BK) {
        // commit staged regs to SMEM (transposed: As[k][row])
        As[ldK + 0][ldRow] = ra0.x; As[ldK + 1][ldRow] = ra0.y;
        As[ldK + 2][ldRow] = ra0.z; As[ldK + 3][ldRow] = ra0.w;
        As[ldK + 4][ldRow] = ra1.x; As[ldK + 5][ldRow] = ra1.y;
        As[ldK + 6][ldRow] = ra1.z; As[ldK + 7][ldRow] = ra1.w;
        Bs[ldK + 0][ldRow] = rb0.x; Bs[ldK + 1][ldRow] = rb0.y;
        Bs[ldK + 2][ldRow] = rb0.z; Bs[ldK + 3][ldRow] = rb0.w;
        Bs[ldK + 4][ldRow] = rb1.x; Bs[ldK + 5][ldRow] = rb1.y;
        Bs[ldK + 6][ldRow] = rb1.z; Bs[ldK + 7][ldRow] = rb1.w;
        __syncthreads();

        // prefetch next k-tile while computing this one
        if (kt + BK < D) {
            const int k0 = kt + BK + ldK;
            float4 x0 = *(const float4*)(aPtr + k0);
            float4 x1 = *(const float4*)(aPtr + k0 + 4);
            float4 e0 = *(const float4*)(ePtr + k0);
            float4 e1 = *(const float4*)(ePtr + k0 + 4);
            ra0 = make_float4(x0.x + e0.x, x0.y + e0.y, x0.z + e0.z, x0.w + e0.w);
            ra1 = make_float4(x1.x + e1.x, x1.y + e1.y, x1.z + e1.z, x1.w + e1.w);
            rb0 = *(const float4*)(bPtr + k0);
            rb1 = *(const float4*)(bPtr + k0 + 4);
        }

        #pragma unroll
        for (int k = 0; k < BK; k++) {
            float4 a0 = *(const float4*)&As[k][ty * 4];
            float4 a1 = *(const float4*)&As[k][ty * 4 + 64];
            float4 b0 = *(const float4*)&Bs[k][tx * 4];
            float4 b1 = *(const float4*)&Bs[k][tx * 4 + 64];
            float a[8] = {a0.x, a0.y, a0.z, a0.w, a1.x, a1.y, a1.z, a1.w};
            float b[8] = {b0.x, b0.y, b0.z, b0.w, b1.x, b1.y, b1.z, b1.w};
            #pragma unroll
            for (int i = 0; i < 8; i++)
                #pragma unroll
                for (int j = 0; j < 8; j++)
                    acc[i][j] = fmaf(a[i], b[j], acc[i][j]);
        }
        __syncthreads();
    }

    // ---- epilogue: bias, relu, gate, relu ----
    const float zeta = g_zeta;
    float btv[8];
    {
        float4 t0 = *(const float4*)(bt + colBase + tx * 4);
        float4 t1 = *(const float4*)(bt + colBase + tx * 4 + 64);
        btv[0] = t0.x; btv[1] = t0.y; btv[2] = t0.z; btv[3] = t0.w;
        btv[4] = t1.x; btv[5] = t1.y; btv[6] = t1.z; btv[7] = t1.w;
    }
    #pragma unroll
    for (int i = 0; i < 8; i++) {
        const int row = rowBase + (i >> 2) * 64 + ty * 4 + (i & 3);
        const float mwz = mw[row % M] * zeta;
        float4 o0, o1;
        o0.x = fmaxf(mwz * fmaxf(acc[i][0] + btv[0], 0.f), 0.f);
        o0.y = fmaxf(mwz * fmaxf(acc[i][1] + btv[1], 0.f), 0.f);
        o0.z = fmaxf(mwz * fmaxf(acc[i][2] + btv[2], 0.f), 0.f);
        o0.w = fmaxf(mwz * fmaxf(acc[i][3] + btv[3], 0.f), 0.f);
        o1.x = fmaxf(mwz * fmaxf(acc[i][4] + btv[4], 0.f), 0.f);
        o1.y = fmaxf(mwz * fmaxf(acc[i][5] + btv[5], 0.f), 0.f);
        o1.z = fmaxf(mwz * fmaxf(acc[i][6] + btv[6], 0.f), 0.f);
        o1.w = fmaxf(mwz * fmaxf(acc[i][7] + btv[7], 0.f), 0.f);
        float* op = out + (size_t)row * D + colBase + tx * 4;
        *(float4*)(op)      = o0;
        *(float4*)(op + 64) = o1;
    }
}

extern "C" void kernel_launch(void* const* d_in, const int* in_sizes, int n_in,
                              void* d_out, int out_size) {
    const float* x    = (const float*)d_in[0];
    const int*   ids  = (const int*)  d_in[1];
    const float* mw   = (const float*)d_in[2];
    const float* emb  = (const float*)d_in[3];
    const float* Wt   = (const float*)d_in[4];
    const float* bt   = (const float*)d_in[5];
    const float* Wrc  = (const float*)d_in[6];
    const float* brc  = (const float*)d_in[7];

    const int D     = in_sizes[5];        // 2048
    const int M     = in_sizes[2];        // 2
    const int Nrows = in_sizes[1];        // B*M = 8192

    zeta_kernel<<<1, 256>>>(Wrc, brc, D);

    dim3 grid(D / BN, Nrows / BM);        // (16, 64)
    redaf_gemm<<<grid, 256>>>(x, ids, mw, emb, Wt, bt, (float*)d_out,
                              Nrows, D, M);
}

// round 3
// speedup vs baseline: 1.6924x; 1.6924x over previous
#include <cuda_runtime.h>
#include <cuda_bf16.h>
#include <cstdint>

#define REL_CONTEXT 0.2f

// ---------------- problem dims (fixed) ----------------
#define NROWS 8192
#define DIM   2048
#define BM    128
#define BN    128
#define BK    64
#define NCH   (DIM / BK)       // 32

// ---------------- scratch ----------------
__device__ __align__(128) __nv_bfloat16 g_Ahi[(size_t)NROWS * DIM];
__device__ __align__(128) __nv_bfloat16 g_Alo[(size_t)NROWS * DIM];
__device__ __align__(128) __nv_bfloat16 g_Whi[(size_t)DIM * DIM];
__device__ __align__(128) __nv_bfloat16 g_Wlo[(size_t)DIM * DIM];
__device__ float g_zeta;

// ---------------- PTX helpers (base-target only) ----------------
__device__ __forceinline__ uint32_t smem_to_u32(const void* p) {
    uint32_t a;
    asm("{ .reg .u64 t; cvta.to.shared.u64 t, %1; cvt.u32.u64 %0, t; }"
        : "=r"(a) : "l"(p));
    return a;
}
#define MBARRIER_INIT(addr, cnt) \
    asm volatile("mbarrier.init.shared.b64 [%0], %1;" :: "r"((uint32_t)(addr)), "r"((uint32_t)(cnt)) : "memory")
#define MBARRIER_EXPECT_TX(addr, bytes) \
    asm volatile("mbarrier.arrive.expect_tx.shared.b64 _, [%0], %1;" \
                 :: "r"((uint32_t)(addr)), "r"((uint32_t)(bytes)) : "memory")
#define MBARRIER_WAIT_PARITY(addr, par) do { \
    uint32_t _m = (uint32_t)(addr); uint32_t _p = (uint32_t)(par); uint32_t _d; \
    asm volatile("{\n\t.reg .pred p;\n\t" \
        "mbarrier.try_wait.parity.acquire.cta.shared::cta.b64 p, [%1], %2;\n\t" \
        "selp.b32 %0, 1, 0, p;\n\t}" : "=r"(_d) : "r"(_m), "r"(_p) : "memory"); \
    if (!_d) { \
        asm volatile("{\n\t.reg .pred P1;\n\t" \
            "WL_%=:\n\t" \
            "mbarrier.try_wait.parity.acquire.cta.shared::cta.b64 P1, [%0], %1, 0x989680;\n\t" \
            "@P1 bra.uni WD_%=;\n\tbra.uni WL_%=;\n\tWD_%=:\n\t}" \
            :: "r"(_m), "r"(_p) : "memory"); \
    } } while (0)
#define BULK_G2S(dst, src, bytes, mbar) \
    asm volatile("cp.async.bulk.shared::cluster.global.mbarrier::complete_tx::bytes " \
                 "[%0], [%1], %2, [%3];" \
                 :: "r"((uint32_t)(dst)), "l"(src), "r"((uint32_t)(bytes)), \
                    "r"((uint32_t)(mbar)) : "memory")

#define LDMATRIX_X4(r0, r1, r2, r3, addr) \
    asm volatile("ldmatrix.sync.aligned.m8n8.x4.shared.b16 {%0,%1,%2,%3}, [%4];" \
                 : "=r"(r0), "=r"(r1), "=r"(r2), "=r"(r3) : "r"(addr))

#define MMA_BF16(d, a, b) \
    asm volatile("mma.sync.aligned.m16n8k16.row.col.f32.bf16.bf16.f32 " \
                 "{%0,%1,%2,%3}, {%4,%5,%6,%7}, {%8,%9}, {%0,%1,%2,%3};" \
                 : "+f"((d)[0]), "+f"((d)[1]), "+f"((d)[2]), "+f"((d)[3]) \
                 : "r"((a)[0]), "r"((a)[1]), "r"((a)[2]), "r"((a)[3]), \
                   "r"((b)[0]), "r"((b)[1]))

// ---------------- smem layout ----------------
#define SM_BAR   0                    // 2 x 8B mbarriers
#define SM_BIAS  64                   // 128 floats
#define SM_TILES 1024
#define T_AHI    0
#define T_ALO    16384
#define T_BHI    32768
#define T_BLO    49152
#define STAGE    65536                // bytes per stage
#define SMEM_TOTAL (SM_TILES + 2 * STAGE)   // 132096

// ---------------- prep kernels ----------------
__global__ void zeta_kernel(const float* __restrict__ Wrc,
                            const float* __restrict__ brc) {
    __shared__ float red[32];
    float s = 0.f;
    for (int i = threadIdx.x; i < DIM; i += blockDim.x) s += Wrc[i];
    #pragma unroll
    for (int o = 16; o > 0; o >>= 1) s += __shfl_down_sync(0xffffffffu, s, o);
    if ((threadIdx.x & 31) == 0) red[threadIdx.x >> 5] = s;
    __syncthreads();
    if (threadIdx.x < 32) {
        float v = (threadIdx.x < (int)(blockDim.x >> 5)) ? red[threadIdx.x] : 0.f;
        #pragma unroll
        for (int o = 16; o > 0; o >>= 1) v += __shfl_down_sync(0xffffffffu, v, o);
        if (threadIdx.x == 0)
            g_zeta = 1.f / (1.f + expf(-(REL_CONTEXT * v + brc[0])));
    }
}

__device__ __forceinline__ void split2(float v, __nv_bfloat16& hi, __nv_bfloat16& lo) {
    hi = __float2bfloat16(v);
    lo = __float2bfloat16(v - __bfloat162float(hi));
}

// writes hi/lo bf16 with 16B-chunk permutation (c ^ (row&7)) inside each 128B row
__device__ __forceinline__ void split_store(__nv_bfloat16* hiArr, __nv_bfloat16* loArr,
                                            int row, int c4, const float v[4]) {
    __nv_bfloat16 h[4], l[4];
    #pragma unroll
    for (int i = 0; i < 4; i++) split2(v[i], h[i], l[i]);
    uint2 hv = make_uint2(
        (uint32_t)*(const uint16_t*)&h[0] | ((uint32_t)*(const uint16_t*)&h[1] << 16),
        (uint32_t)*(const uint16_t*)&h[2] | ((uint32_t)*(const uint16_t*)&h[3] << 16));
    uint2 lv = make_uint2(
        (uint32_t)*(const uint16_t*)&l[0] | ((uint32_t)*(const uint16_t*)&l[1] << 16),
        (uint32_t)*(const uint16_t*)&l[2] | ((uint32_t)*(const uint16_t*)&l[3] << 16));
    const int k0 = c4 * 4;
    const int chunk = k0 >> 3;              // 16B chunk index within row (0..255? no: 0..DIM/8-1)
    const int cIn = chunk & 7;              // chunk within 128B block
    const int blk = chunk >> 3;             // which 128B block
    const int perm = (cIn ^ (row & 7));
    const int h8 = (k0 >> 2) & 1;           // which 8B half of the 16B chunk
    const size_t byteOff = (size_t)row * (DIM * 2) + (size_t)blk * 128 + perm * 16 + h8 * 8;
    *(uint2*)((char*)hiArr + byteOff) = hv;
    *(uint2*)((char*)loArr + byteOff) = lv;
}

__global__ void split_x_kernel(const float* __restrict__ x,
                               const int* __restrict__ ids,
                               const float* __restrict__ emb) {
    const int row = blockIdx.x;
    const int c4 = threadIdx.x;             // 512 threads * 4 floats = 2048
    const int id = ids[row];
    float4 xv = ((const float4*)(x + (size_t)row * DIM))[c4];
    float4 ev = ((const float4*)(emb + (size_t)id * DIM))[c4];
    float v[4] = {xv.x + ev.x, xv.y + ev.y, xv.z + ev.z, xv.w + ev.w};
    split_store(g_Ahi, g_Alo, row, c4, v);
}

__global__ void split_w_kernel(const float* __restrict__ Wt) {
    const int row = blockIdx.x;
    const int c4 = threadIdx.x;
    float4 wv = ((const float4*)(Wt + (size_t)row * DIM))[c4];
    float v[4] = {wv.x, wv.y, wv.z, wv.w};
    split_store(g_Whi, g_Wlo, row, c4, v);
}

// ---------------- main MMA kernel ----------------
__global__ __launch_bounds__(256, 1)
void redaf_mma(const float* __restrict__ mw,
               const float* __restrict__ bt,
               float* __restrict__ out) {
    extern __shared__ char smem[];
    const uint32_t sb = smem_to_u32(smem);
    const int tid = threadIdx.x;
    const int wid = tid >> 5;
    const int lid = tid & 31;

    const int colBase = blockIdx.x * BN;
    const int rowBase = blockIdx.y * BM;

    if (tid < 2) MBARRIER_INIT(sb + SM_BAR + 8 * tid, 1);
    if (tid < BN) ((float*)(smem + SM_BIAS))[tid] = bt[colBase + tid];
    __syncthreads();
    if (tid == 0) {
        MBARRIER_EXPECT_TX(sb + SM_BAR + 0, STAGE);
        MBARRIER_EXPECT_TX(sb + SM_BAR + 8, STAGE);
    }
    __syncthreads();

    // ---- bulk load: 512 row-copies (128B each) per chunk ----
    auto issue_loads = [&](int c, int st) {
        const uint32_t stBase = sb + SM_TILES + st * STAGE;
        const uint32_t mbar = sb + SM_BAR + 8 * st;
        #pragma unroll
        for (int i = 0; i < 2; i++) {
            const int idx = tid + i * 256;          // 0..511
            const int a = idx >> 7;                 // which array
            const int r = idx & 127;
            const char* g;
            size_t grow;
            if (a == 0)      { g = (const char*)g_Ahi; grow = (size_t)(rowBase + r); }
            else if (a == 1) { g = (const char*)g_Alo; grow = (size_t)(rowBase + r); }
            else if (a == 2) { g = (const char*)g_Whi; grow = (size_t)(colBase + r); }
            else             { g = (const char*)g_Wlo; grow = (size_t)(colBase + r); }
            const char* src = g + grow * (DIM * 2) + (size_t)c * 128;
            const uint32_t dst = stBase + a * 16384 + r * 128;
            BULK_G2S(dst, src, 128, mbar);
        }
    };

    issue_loads(0, 0);
    issue_loads(1, 1);

    // ---- per-lane ldmatrix address pieces ----
    const int warpM = wid & 1;          // 2 row-groups of 64
    const int warpN = wid >> 1;         // 4 col-groups of 32
    // A: lanes 0-15 -> rows m0-15 (khalf 0), lanes 16-31 -> same rows (khalf 1)
    const int aRowL = warpM * 64 + (lid & 15);
    const int aKhalf = lid >> 4;
    // B: row = n, +8 for lanes>=16; khalf from bit3
    const int bRowL = warpN * 32 + (lid & 7) + ((lid >> 4) & 1) * 8;
    const int bKhalf = (lid >> 3) & 1;

    float acc[4][4][4];
    #pragma unroll
    for (int i = 0; i < 4; i++)
        #pragma unroll
        for (int j = 0; j < 4; j++)
            #pragma unroll
            for (int k = 0; k < 4; k++) acc[i][j][k] = 0.f;

    #pragma unroll 1
    for (int c = 0; c < NCH; c++) {
        const int st = c & 1;
        const uint32_t mbar = sb + SM_BAR + 8 * st;
        MBARRIER_WAIT_PARITY(mbar, (c >> 1) & 1);
        if (tid == 0 && c + 2 < NCH) MBARRIER_EXPECT_TX(mbar, STAGE);

        const uint32_t stBase = sb + SM_TILES + st * STAGE;
        #pragma unroll
        for (int ks = 0; ks < BK / 16; ks++) {
            uint32_t ahi[4][4], alo[4][4], bhi[4][2], blo[4][2];
            // A fragments
            #pragma unroll
            for (int mt = 0; mt < 4; mt++) {
                const int row = aRowL + mt * 16;
                const int ch = 2 * ks + aKhalf;
                const uint32_t off = row * 128 + ((ch ^ (row & 7)) << 4);
                LDMATRIX_X4(ahi[mt][0], ahi[mt][1], ahi[mt][2], ahi[mt][3],
                            stBase + T_AHI + off);
                LDMATRIX_X4(alo[mt][0], alo[mt][1], alo[mt][2], alo[mt][3],
                            stBase + T_ALO + off);
            }
            // B fragments (x4 covers two n-tiles)
            #pragma unroll
            for (int p = 0; p < 2; p++) {
                const int row = bRowL + p * 16;
                const int ch = 2 * ks + bKhalf;
                const uint32_t off = row * 128 + ((ch ^ (row & 7)) << 4);
                LDMATRIX_X4(bhi[2 * p][0], bhi[2 * p][1], bhi[2 * p + 1][0], bhi[2 * p + 1][1],
                            stBase + T_BHI + off);
                LDMATRIX_X4(blo[2 * p][0], blo[2 * p][1], blo[2 * p + 1][0], blo[2 * p + 1][1],
                            stBase + T_BLO + off);
            }
            // 3 split terms, tiles inner for independence
            #pragma unroll
            for (int mt = 0; mt < 4; mt++)
                #pragma unroll
                for (int nt = 0; nt < 4; nt++) MMA_BF16(acc[mt][nt], ahi[mt], bhi[nt]);
            #pragma unroll
            for (int mt = 0; mt < 4; mt++)
                #pragma unroll
                for (int nt = 0; nt < 4; nt++) MMA_BF16(acc[mt][nt], ahi[mt], blo[nt]);
            #pragma unroll
            for (int mt = 0; mt < 4; mt++)
                #pragma unroll
                for (int nt = 0; nt < 4; nt++) MMA_BF16(acc[mt][nt], alo[mt], bhi[nt]);
        }
        __syncthreads();
        if (c + 2 < NCH) issue_loads(c + 2, st);
    }

    // ---- epilogue ----
    const float zeta = g_zeta;
    const float mwz0 = mw[0] * zeta;
    const float mwz1 = mw[1] * zeta;
    const float* bsm = (const float*)(smem + SM_BIAS);

    #pragma unroll
    for (int mt = 0; mt < 4; mt++) {
        #pragma unroll
        for (int nt = 0; nt < 4; nt++) {
            const int m0 = rowBase + warpM * 64 + mt * 16 + (lid >> 2);
            const int cLoc = warpN * 32 + nt * 8 + 2 * (lid & 3);
            const float b0 = bsm[cLoc], b1 = bsm[cLoc + 1];
            const float mz0 = (m0 & 1) ? mwz1 : mwz0;          // rows m0 and m0+8 same parity
            float2 o0, o1;
            o0.x = fmaxf(mz0 * fmaxf(acc[mt][nt][0] + b0, 0.f), 0.f);
            o0.y = fmaxf(mz0 * fmaxf(acc[mt][nt][1] + b1, 0.f), 0.f);
            o1.x = fmaxf(mz0 * fmaxf(acc[mt][nt][2] + b0, 0.f), 0.f);
            o1.y = fmaxf(mz0 * fmaxf(acc[mt][nt][3] + b1, 0.f), 0.f);
            float* p0 = out + (size_t)m0 * DIM + colBase + cLoc;
            *(float2*)p0 = o0;
            *(float2*)(p0 + (size_t)8 * DIM) = o1;
        }
    }
}

// ---------------- launch ----------------
extern "C" void kernel_launch(void* const* d_in, const int* in_sizes, int n_in,
                              void* d_out, int out_size) {
    const float* x   = (const float*)d_in[0];
    const int*   ids = (const int*)  d_in[1];
    const float* mw  = (const float*)d_in[2];
    const float* emb = (const float*)d_in[3];
    const float* Wt  = (const float*)d_in[4];
    const float* bt  = (const float*)d_in[5];
    const float* Wrc = (const float*)d_in[6];
    const float* brc = (const float*)d_in[7];

    cudaFuncSetAttribute(redaf_mma, cudaFuncAttributeMaxDynamicSharedMemorySize,
                         SMEM_TOTAL);

    zeta_kernel<<<1, 256>>>(Wrc, brc);
    split_x_kernel<<<NROWS, 512>>>(x, ids, emb);
    split_w_kernel<<<DIM, 512>>>(Wt);

    dim3 grid(DIM / BN, NROWS / BM);   // (16, 64)
    redaf_mma<<<grid, 256, SMEM_TOTAL>>>(mw, bt, (float*)d_out);
}

// round 4
// speedup vs baseline: 4.5688x; 2.6997x over previous
#include <cuda_runtime.h>
#include <cuda_fp16.h>
#include <cstdint>

#define REL_CONTEXT 0.2f

// ---------------- problem dims (fixed) ----------------
#define NROWS 8192
#define DIM   2048
#define BM    128
#define BN    128
#define BK    64
#define NCH   (DIM / BK)       // 32
#define NSTAGE 4

// ---------------- scratch (chunk-major, pre-swizzled) ----------------
// layout: block for (chunk c, row r) is 128 bytes at ((c*NROWS_or_DIM + r) * 128),
// with the eight 16B sub-chunks permuted by (ci ^ (r & 7)).
__device__ __align__(128) __half g_Ahi[(size_t)NROWS * DIM];
__device__ __align__(128) __half g_Alo[(size_t)NROWS * DIM];
__device__ __align__(128) __half g_Wh [(size_t)DIM * DIM];
__device__ float g_zeta;

// ---------------- PTX helpers (base-target only) ----------------
__device__ __forceinline__ uint32_t smem_to_u32(const void* p) {
    uint32_t a;
    asm("{ .reg .u64 t; cvta.to.shared.u64 t, %1; cvt.u32.u64 %0, t; }"
        : "=r"(a) : "l"(p));
    return a;
}
#define MBARRIER_INIT(addr, cnt) \
    asm volatile("mbarrier.init.shared.b64 [%0], %1;" :: "r"((uint32_t)(addr)), "r"((uint32_t)(cnt)) : "memory")
#define MBARRIER_ARRIVE(addr) \
    asm volatile("mbarrier.arrive.shared.b64 _, [%0];" :: "r"((uint32_t)(addr)) : "memory")
#define MBARRIER_EXPECT_TX(addr, bytes) \
    asm volatile("mbarrier.arrive.expect_tx.shared.b64 _, [%0], %1;" \
                 :: "r"((uint32_t)(addr)), "r"((uint32_t)(bytes)) : "memory")
#define MBARRIER_WAIT_PARITY(addr, par) do { \
    uint32_t _m = (uint32_t)(addr); uint32_t _p = (uint32_t)(par); uint32_t _d; \
    asm volatile("{\n\t.reg .pred p;\n\t" \
        "mbarrier.try_wait.parity.acquire.cta.shared::cta.b64 p, [%1], %2;\n\t" \
        "selp.b32 %0, 1, 0, p;\n\t}" : "=r"(_d) : "r"(_m), "r"(_p) : "memory"); \
    if (!_d) { \
        asm volatile("{\n\t.reg .pred P1;\n\t" \
            "WL_%=:\n\t" \
            "mbarrier.try_wait.parity.acquire.cta.shared::cta.b64 P1, [%0], %1, 0x989680;\n\t" \
            "@P1 bra.uni WD_%=;\n\tbra.uni WL_%=;\n\tWD_%=:\n\t}" \
            :: "r"(_m), "r"(_p) : "memory"); \
    } } while (0)
#define BULK_G2S(dst, src, bytes, mbar) \
    asm volatile("cp.async.bulk.shared::cluster.global.mbarrier::complete_tx::bytes " \
                 "[%0], [%1], %2, [%3];" \
                 :: "r"((uint32_t)(dst)), "l"(src), "r"((uint32_t)(bytes)), \
                    "r"((uint32_t)(mbar)) : "memory")
#define LDMATRIX_X4(r0, r1, r2, r3, addr) \
    asm volatile("ldmatrix.sync.aligned.m8n8.x4.shared.b16 {%0,%1,%2,%3}, [%4];" \
                 : "=r"(r0), "=r"(r1), "=r"(r2), "=r"(r3) : "r"(addr))
#define MMA_F16(d, a, b) \
    asm volatile("mma.sync.aligned.m16n8k16.row.col.f32.f16.f16.f32 " \
                 "{%0,%1,%2,%3}, {%4,%5,%6,%7}, {%8,%9}, {%0,%1,%2,%3};" \
                 : "+f"((d)[0]), "+f"((d)[1]), "+f"((d)[2]), "+f"((d)[3]) \
                 : "r"((a)[0]), "r"((a)[1]), "r"((a)[2]), "r"((a)[3]), \
                   "r"((b)[0]), "r"((b)[1]))

// ---------------- smem layout ----------------
#define SM_BAR   0                    // full[s] at 16*s, empty[s] at 16*s+8
#define SM_BIAS  128                  // 128 floats
#define SM_TILES 1024
#define T_AHI    0
#define T_ALO    16384
#define T_BH     32768
#define STAGE_BYTES 49152             // 3 x 16KB
#define SMEM_TOTAL (SM_TILES + NSTAGE * STAGE_BYTES)   // 197632

// ---------------- prep kernels ----------------
__global__ void zeta_kernel(const float* __restrict__ Wrc,
                            const float* __restrict__ brc) {
    __shared__ float red[32];
    float s = 0.f;
    for (int i = threadIdx.x; i < DIM; i += blockDim.x) s += Wrc[i];
    #pragma unroll
    for (int o = 16; o > 0; o >>= 1) s += __shfl_down_sync(0xffffffffu, s, o);
    if ((threadIdx.x & 31) == 0) red[threadIdx.x >> 5] = s;
    __syncthreads();
    if (threadIdx.x < 32) {
        float v = (threadIdx.x < (int)(blockDim.x >> 5)) ? red[threadIdx.x] : 0.f;
        #pragma unroll
        for (int o = 16; o > 0; o >>= 1) v += __shfl_down_sync(0xffffffffu, v, o);
        if (threadIdx.x == 0)
            g_zeta = 1.f / (1.f + expf(-(REL_CONTEXT * v + brc[0])));
    }
}

// chunk-major, swizzled byte offset for (row, k0) with 4 consecutive halves (8B)
__device__ __forceinline__ size_t scratch_off(int nTotRows, int row, int k0) {
    const int chunk = k0 >> 6;
    const int kc = k0 & 63;
    const int ci = kc >> 3;
    const int h8 = (kc >> 2) & 1;
    return ((size_t)chunk * nTotRows + row) * 128 + ((ci ^ (row & 7)) << 4) + h8 * 8;
}

__global__ void split_x_kernel(const float* __restrict__ x,
                               const int* __restrict__ ids,
                               const float* __restrict__ emb) {
    const int row = blockIdx.x;
    const int c4 = threadIdx.x;             // 512 threads * 4 floats = 2048
    const int id = ids[row];
    float4 xv = ((const float4*)(x + (size_t)row * DIM))[c4];
    float4 ev = ((const float4*)(emb + (size_t)id * DIM))[c4];
    float v[4] = {xv.x + ev.x, xv.y + ev.y, xv.z + ev.z, xv.w + ev.w};
    uint16_t h[4], l[4];
    #pragma unroll
    for (int i = 0; i < 4; i++) {
        __half hi = __float2half_rn(v[i]);
        __half lo = __float2half_rn(v[i] - __half2float(hi));
        h[i] = *(uint16_t*)&hi;
        l[i] = *(uint16_t*)&lo;
    }
    uint2 hv = make_uint2((uint32_t)h[0] | ((uint32_t)h[1] << 16),
                          (uint32_t)h[2] | ((uint32_t)h[3] << 16));
    uint2 lv = make_uint2((uint32_t)l[0] | ((uint32_t)l[1] << 16),
                          (uint32_t)l[2] | ((uint32_t)l[3] << 16));
    const size_t off = scratch_off(NROWS, row, c4 * 4);
    *(uint2*)((char*)g_Ahi + off) = hv;
    *(uint2*)((char*)g_Alo + off) = lv;
}

__global__ void round_w_kernel(const float* __restrict__ Wt) {
    const int row = blockIdx.x;
    const int c4 = threadIdx.x;
    float4 wv = ((const float4*)(Wt + (size_t)row * DIM))[c4];
    float v[4] = {wv.x, wv.y, wv.z, wv.w};
    uint16_t h[4];
    #pragma unroll
    for (int i = 0; i < 4; i++) {
        __half hi = __float2half_rn(v[i]);
        h[i] = *(uint16_t*)&hi;
    }
    uint2 hv = make_uint2((uint32_t)h[0] | ((uint32_t)h[1] << 16),
                          (uint32_t)h[2] | ((uint32_t)h[3] << 16));
    *(uint2*)((char*)g_Wh + scratch_off(DIM, row, c4 * 4)) = hv;
}

// ---------------- main MMA kernel ----------------
__global__ __launch_bounds__(256, 1)
void redaf_mma(const float* __restrict__ mw,
               const float* __restrict__ bt,
               float* __restrict__ out) {
    extern __shared__ char smem[];
    const uint32_t sb = smem_to_u32(smem);
    const int tid = threadIdx.x;
    const int wid = tid >> 5;
    const int lid = tid & 31;

    const int colBase = blockIdx.x * BN;
    const int rowBase = blockIdx.y * BM;

    if (tid == 0) {
        #pragma unroll
        for (int s = 0; s < NSTAGE; s++) {
            MBARRIER_INIT(sb + SM_BAR + 16 * s, 1);        // full: 1 expect_tx arrive
            MBARRIER_INIT(sb + SM_BAR + 16 * s + 8, 8);    // empty: 8 warps
        }
    }
    if (tid < BN) ((float*)(smem + SM_BIAS))[tid] = bt[colBase + tid];
    __syncthreads();

    // ---- producer: 3 bulk copies of 16KB per chunk ----
    auto produce = [&](int c) {
        const int s = c & 3;
        const uint32_t stB = sb + SM_TILES + s * STAGE_BYTES;
        const uint32_t fb = sb + SM_BAR + 16 * s;
        MBARRIER_EXPECT_TX(fb, STAGE_BYTES);
        BULK_G2S(stB + T_AHI,
                 (const char*)g_Ahi + ((size_t)c * NROWS + rowBase) * 128, 16384, fb);
        BULK_G2S(stB + T_ALO,
                 (const char*)g_Alo + ((size_t)c * NROWS + rowBase) * 128, 16384, fb);
        BULK_G2S(stB + T_BH,
                 (const char*)g_Wh + ((size_t)c * DIM + colBase) * 128, 16384, fb);
    };

    // prefill: warp s's lane 0 fills stage s
    if (lid == 0 && wid < NSTAGE) produce(wid);

    // ---- per-lane ldmatrix address pieces (validated round 3 mapping) ----
    const int warpM = wid & 1;
    const int warpN = wid >> 1;
    const int aRowL = warpM * 64 + (lid & 15);
    const int aKhalf = lid >> 4;
    const int bRowL = warpN * 32 + (lid & 7) + ((lid >> 4) & 1) * 8;
    const int bKhalf = (lid >> 3) & 1;

    float acc[4][4][4];
    #pragma unroll
    for (int i = 0; i < 4; i++)
        #pragma unroll
        for (int j = 0; j < 4; j++)
            #pragma unroll
            for (int k = 0; k < 4; k++) acc[i][j][k] = 0.f;

    #pragma unroll 1
    for (int c = 0; c < NCH; c++) {
        const int s = c & 3;
        const uint32_t par = (c >> 2) & 1;
        const uint32_t fullB = sb + SM_BAR + 16 * s;
        const uint32_t emptyB = fullB + 8;
        MBARRIER_WAIT_PARITY(fullB, par);

        const uint32_t stBase = sb + SM_TILES + s * STAGE_BYTES;
        #pragma unroll
        for (int ks = 0; ks < BK / 16; ks++) {
            uint32_t ahi[4][4], alo[4][4], bh[4][2];
            #pragma unroll
            for (int mt = 0; mt < 4; mt++) {
                const int row = aRowL + mt * 16;
                const int ch = 2 * ks + aKhalf;
                const uint32_t off = row * 128 + ((ch ^ (row & 7)) << 4);
                LDMATRIX_X4(ahi[mt][0], ahi[mt][1], ahi[mt][2], ahi[mt][3],
                            stBase + T_AHI + off);
                LDMATRIX_X4(alo[mt][0], alo[mt][1], alo[mt][2], alo[mt][3],
                            stBase + T_ALO + off);
            }
            #pragma unroll
            for (int p = 0; p < 2; p++) {
                const int row = bRowL + p * 16;
                const int ch = 2 * ks + bKhalf;
                const uint32_t off = row * 128 + ((ch ^ (row & 7)) << 4);
                LDMATRIX_X4(bh[2 * p][0], bh[2 * p][1], bh[2 * p + 1][0], bh[2 * p + 1][1],
                            stBase + T_BH + off);
            }
            #pragma unroll
            for (int mt = 0; mt < 4; mt++)
                #pragma unroll
                for (int nt = 0; nt < 4; nt++) MMA_F16(acc[mt][nt], ahi[mt], bh[nt]);
            #pragma unroll
            for (int mt = 0; mt < 4; mt++)
                #pragma unroll
                for (int nt = 0; nt < 4; nt++) MMA_F16(acc[mt][nt], alo[mt], bh[nt]);
        }

        if (lid == 0) {
            MBARRIER_ARRIVE(emptyB);
            if (wid == s && c + NSTAGE < NCH) {
                MBARRIER_WAIT_PARITY(emptyB, par);
                produce(c + NSTAGE);
            }
        }
    }

    // ---- epilogue: bias -> relu -> mw*zeta -> relu ----
    const float zeta = g_zeta;
    const float mwz0 = mw[0] * zeta;
    const float mwz1 = mw[1] * zeta;
    const float* bsm = (const float*)(smem + SM_BIAS);

    #pragma unroll
    for (int mt = 0; mt < 4; mt++) {
        #pragma unroll
        for (int nt = 0; nt < 4; nt++) {
            const int m0 = rowBase + warpM * 64 + mt * 16 + (lid >> 2);
            const int cLoc = warpN * 32 + nt * 8 + 2 * (lid & 3);
            const float b0 = bsm[cLoc], b1 = bsm[cLoc + 1];
            const float mz = (m0 & 1) ? mwz1 : mwz0;
            float2 o0, o1;
            o0.x = fmaxf(mz * fmaxf(acc[mt][nt][0] + b0, 0.f), 0.f);
            o0.y = fmaxf(mz * fmaxf(acc[mt][nt][1] + b1, 0.f), 0.f);
            o1.x = fmaxf(mz * fmaxf(acc[mt][nt][2] + b0, 0.f), 0.f);
            o1.y = fmaxf(mz * fmaxf(acc[mt][nt][3] + b1, 0.f), 0.f);
            float* p0 = out + (size_t)m0 * DIM + colBase + cLoc;
            *(float2*)p0 = o0;
            *(float2*)(p0 + (size_t)8 * DIM) = o1;
        }
    }
}

// ---------------- launch ----------------
extern "C" void kernel_launch(void* const* d_in, const int* in_sizes, int n_in,
                              void* d_out, int out_size) {
    const float* x   = (const float*)d_in[0];
    const int*   ids = (const int*)  d_in[1];
    const float* mw  = (const float*)d_in[2];
    const float* emb = (const float*)d_in[3];
    const float* Wt  = (const float*)d_in[4];
    const float* bt  = (const float*)d_in[5];
    const float* Wrc = (const float*)d_in[6];
    const float* brc = (const float*)d_in[7];

    cudaFuncSetAttribute(redaf_mma, cudaFuncAttributeMaxDynamicSharedMemorySize,
                         SMEM_TOTAL);

    zeta_kernel<<<1, 256>>>(Wrc, brc);
    split_x_kernel<<<NROWS, 512>>>(x, ids, emb);
    round_w_kernel<<<DIM, 512>>>(Wt);

    dim3 grid(DIM / BN, NROWS / BM);   // (16, 64)
    redaf_mma<<<grid, 256, SMEM_TOTAL>>>(mw, bt, (float*)d_out);
}

// round 5
// speedup vs baseline: 7.7754x; 1.7018x over previous
#include <cuda_runtime.h>
#include <cuda_fp16.h>
#include <cstdint>

#define REL_CONTEXT 0.2f

// ---------------- problem dims (fixed) ----------------
#define NROWS 8192
#define DIM   2048
#define BM    128
#define BN    128
#define BK    64
#define NCH   (DIM / BK)       // 32
#define NSTAGE 3

// ---------------- scratch (chunk-major, pre-swizzled fp16) ----------------
// block for (chunk c, row r) is 128 bytes at ((c*nRows + r) * 128),
// eight 16B sub-chunks permuted by (ci ^ (r & 7)).
__device__ __align__(128) __half g_Ah[(size_t)NROWS * DIM];
__device__ __align__(128) __half g_Wh[(size_t)DIM * DIM];
__device__ float g_zeta;

// ---------------- PTX helpers (base-target only) ----------------
__device__ __forceinline__ uint32_t smem_to_u32(const void* p) {
    uint32_t a;
    asm("{ .reg .u64 t; cvta.to.shared.u64 t, %1; cvt.u32.u64 %0, t; }"
        : "=r"(a) : "l"(p));
    return a;
}
#define MBARRIER_INIT(addr, cnt) \
    asm volatile("mbarrier.init.shared.b64 [%0], %1;" :: "r"((uint32_t)(addr)), "r"((uint32_t)(cnt)) : "memory")
#define MBARRIER_ARRIVE(addr) \
    asm volatile("mbarrier.arrive.shared.b64 _, [%0];" :: "r"((uint32_t)(addr)) : "memory")
#define MBARRIER_EXPECT_TX(addr, bytes) \
    asm volatile("mbarrier.arrive.expect_tx.shared.b64 _, [%0], %1;" \
                 :: "r"((uint32_t)(addr)), "r"((uint32_t)(bytes)) : "memory")
#define MBARRIER_WAIT_PARITY(addr, par) do { \
    uint32_t _m = (uint32_t)(addr); uint32_t _p = (uint32_t)(par); uint32_t _d; \
    asm volatile("{\n\t.reg .pred p;\n\t" \
        "mbarrier.try_wait.parity.acquire.cta.shared::cta.b64 p, [%1], %2;\n\t" \
        "selp.b32 %0, 1, 0, p;\n\t}" : "=r"(_d) : "r"(_m), "r"(_p) : "memory"); \
    if (!_d) { \
        asm volatile("{\n\t.reg .pred P1;\n\t" \
            "WL_%=:\n\t" \
            "mbarrier.try_wait.parity.acquire.cta.shared::cta.b64 P1, [%0], %1, 0x989680;\n\t" \
            "@P1 bra.uni WD_%=;\n\tbra.uni WL_%=;\n\tWD_%=:\n\t}" \
            :: "r"(_m), "r"(_p) : "memory"); \
    } } while (0)
#define BULK_G2S(dst, src, bytes, mbar) \
    asm volatile("cp.async.bulk.shared::cluster.global.mbarrier::complete_tx::bytes " \
                 "[%0], [%1], %2, [%3];" \
                 :: "r"((uint32_t)(dst)), "l"(src), "r"((uint32_t)(bytes)), \
                    "r"((uint32_t)(mbar)) : "memory")
#define LDMATRIX_X4(r0, r1, r2, r3, addr) \
    asm volatile("ldmatrix.sync.aligned.m8n8.x4.shared.b16 {%0,%1,%2,%3}, [%4];" \
                 : "=r"(r0), "=r"(r1), "=r"(r2), "=r"(r3) : "r"(addr))
#define MMA_F16(d, a, b) \
    asm volatile("mma.sync.aligned.m16n8k16.row.col.f32.f16.f16.f32 " \
                 "{%0,%1,%2,%3}, {%4,%5,%6,%7}, {%8,%9}, {%0,%1,%2,%3};" \
                 : "+f"((d)[0]), "+f"((d)[1]), "+f"((d)[2]), "+f"((d)[3]) \
                 : "r"((a)[0]), "r"((a)[1]), "r"((a)[2]), "r"((a)[3]), \
                   "r"((b)[0]), "r"((b)[1]))

// ---------------- smem layout ----------------
#define SM_BAR   0                    // full[s] at 16*s, empty[s] at 16*s+8
#define SM_BIAS  128                  // 128 floats
#define SM_TILES 1024
#define T_AH     0
#define T_BH     16384
#define STAGE_BYTES 32768             // 2 x 16KB
#define SMEM_TOTAL (SM_TILES + NSTAGE * STAGE_BYTES)   // 99328 (2 CTAs/SM)

// ---------------- prep kernels ----------------
__global__ void zeta_kernel(const float* __restrict__ Wrc,
                            const float* __restrict__ brc) {
    __shared__ float red[32];
    float s = 0.f;
    for (int i = threadIdx.x; i < DIM; i += blockDim.x) s += Wrc[i];
    #pragma unroll
    for (int o = 16; o > 0; o >>= 1) s += __shfl_down_sync(0xffffffffu, s, o);
    if ((threadIdx.x & 31) == 0) red[threadIdx.x >> 5] = s;
    __syncthreads();
    if (threadIdx.x < 32) {
        float v = (threadIdx.x < (int)(blockDim.x >> 5)) ? red[threadIdx.x] : 0.f;
        #pragma unroll
        for (int o = 16; o > 0; o >>= 1) v += __shfl_down_sync(0xffffffffu, v, o);
        if (threadIdx.x == 0)
            g_zeta = 1.f / (1.f + expf(-(REL_CONTEXT * v + brc[0])));
    }
}

// chunk-major, swizzled byte offset for (row, k0): 4 consecutive halves (8B)
__device__ __forceinline__ size_t scratch_off(int nTotRows, int row, int k0) {
    const int chunk = k0 >> 6;
    const int kc = k0 & 63;
    const int ci = kc >> 3;
    const int h8 = (kc >> 2) & 1;
    return ((size_t)chunk * nTotRows + row) * 128 + ((ci ^ (row & 7)) << 4) + h8 * 8;
}

__device__ __forceinline__ uint2 pack_h4(const float v[4]) {
    uint16_t h[4];
    #pragma unroll
    for (int i = 0; i < 4; i++) {
        __half hv = __float2half_rn(v[i]);
        h[i] = *(uint16_t*)&hv;
    }
    return make_uint2((uint32_t)h[0] | ((uint32_t)h[1] << 16),
                      (uint32_t)h[2] | ((uint32_t)h[3] << 16));
}

__global__ void prep_x_kernel(const float* __restrict__ x,
                              const int* __restrict__ ids,
                              const float* __restrict__ emb) {
    const int row = blockIdx.x;
    const int c4 = threadIdx.x;             // 512 threads * 4 floats = 2048
    const int id = ids[row];
    float4 xv = ((const float4*)(x + (size_t)row * DIM))[c4];
    float4 ev = ((const float4*)(emb + (size_t)id * DIM))[c4];
    float v[4] = {xv.x + ev.x, xv.y + ev.y, xv.z + ev.z, xv.w + ev.w};
    *(uint2*)((char*)g_Ah + scratch_off(NROWS, row, c4 * 4)) = pack_h4(v);
}

__global__ void prep_w_kernel(const float* __restrict__ Wt) {
    const int row = blockIdx.x;
    const int c4 = threadIdx.x;
    float4 wv = ((const float4*)(Wt + (size_t)row * DIM))[c4];
    float v[4] = {wv.x, wv.y, wv.z, wv.w};
    *(uint2*)((char*)g_Wh + scratch_off(DIM, row, c4 * 4)) = pack_h4(v);
}

// ---------------- main MMA kernel ----------------
__global__ __launch_bounds__(256, 2)
void redaf_mma(const float* __restrict__ mw,
               const float* __restrict__ bt,
               float* __restrict__ out) {
    extern __shared__ char smem[];
    const uint32_t sb = smem_to_u32(smem);
    const int tid = threadIdx.x;
    const int wid = tid >> 5;
    const int lid = tid & 31;

    const int colBase = blockIdx.x * BN;
    const int rowBase = blockIdx.y * BM;

    if (tid == 0) {
        #pragma unroll
        for (int s = 0; s < NSTAGE; s++) {
            MBARRIER_INIT(sb + SM_BAR + 16 * s, 1);        // full: expect_tx
            MBARRIER_INIT(sb + SM_BAR + 16 * s + 8, 8);    // empty: 8 warps
        }
    }
    if (tid < BN) ((float*)(smem + SM_BIAS))[tid] = bt[colBase + tid];
    __syncthreads();

    // ---- producer: 2 bulk copies of 16KB per chunk ----
    auto produce = [&](int c) {
        const int s = c % NSTAGE;
        const uint32_t stB = sb + SM_TILES + s * STAGE_BYTES;
        const uint32_t fb = sb + SM_BAR + 16 * s;
        MBARRIER_EXPECT_TX(fb, STAGE_BYTES);
        BULK_G2S(stB + T_AH,
                 (const char*)g_Ah + ((size_t)c * NROWS + rowBase) * 128, 16384, fb);
        BULK_G2S(stB + T_BH,
                 (const char*)g_Wh + ((size_t)c * DIM + colBase) * 128, 16384, fb);
    };

    // prefill: warp s (s < NSTAGE) lane 0 fills stage s
    if (lid == 0 && wid < NSTAGE) produce(wid);

    // ---- per-lane ldmatrix address pieces (validated mapping) ----
    const int warpM = wid & 1;
    const int warpN = wid >> 1;
    const int aRowL = warpM * 64 + (lid & 15);
    const int aKhalf = lid >> 4;
    const int bRowL = warpN * 32 + (lid & 7) + ((lid >> 4) & 1) * 8;
    const int bKhalf = (lid >> 3) & 1;

    float acc[4][4][4];
    #pragma unroll
    for (int i = 0; i < 4; i++)
        #pragma unroll
        for (int j = 0; j < 4; j++)
            #pragma unroll
            for (int k = 0; k < 4; k++) acc[i][j][k] = 0.f;

    #pragma unroll 1
    for (int c = 0; c < NCH; c++) {
        const int s = c % NSTAGE;
        const uint32_t par = (c / NSTAGE) & 1;
        const uint32_t fullB = sb + SM_BAR + 16 * s;
        const uint32_t emptyB = fullB + 8;
        MBARRIER_WAIT_PARITY(fullB, par);

        const uint32_t stBase = sb + SM_TILES + s * STAGE_BYTES;
        #pragma unroll
        for (int ks = 0; ks < BK / 16; ks++) {
            uint32_t ah[4][4], bh[4][2];
            #pragma unroll
            for (int mt = 0; mt < 4; mt++) {
                const int row = aRowL + mt * 16;
                const int ch = 2 * ks + aKhalf;
                const uint32_t off = row * 128 + ((ch ^ (row & 7)) << 4);
                LDMATRIX_X4(ah[mt][0], ah[mt][1], ah[mt][2], ah[mt][3],
                            stBase + T_AH + off);
            }
            #pragma unroll
            for (int p = 0; p < 2; p++) {
                const int row = bRowL + p * 16;
                const int ch = 2 * ks + bKhalf;
                const uint32_t off = row * 128 + ((ch ^ (row & 7)) << 4);
                LDMATRIX_X4(bh[2 * p][0], bh[2 * p][1], bh[2 * p + 1][0], bh[2 * p + 1][1],
                            stBase + T_BH + off);
            }
            #pragma unroll
            for (int mt = 0; mt < 4; mt++)
                #pragma unroll
                for (int nt = 0; nt < 4; nt++) MMA_F16(acc[mt][nt], ah[mt], bh[nt]);
        }

        if (lid == 0) {
            MBARRIER_ARRIVE(emptyB);
            if (wid == s && c + NSTAGE < NCH) {
                MBARRIER_WAIT_PARITY(emptyB, par);
                produce(c + NSTAGE);
            }
        }
    }

    // ---- epilogue: bias -> relu -> mw*zeta -> relu ----
    const float zeta = g_zeta;
    const float mwz0 = mw[0] * zeta;
    const float mwz1 = mw[1] * zeta;
    const float* bsm = (const float*)(smem + SM_BIAS);

    #pragma unroll
    for (int mt = 0; mt < 4; mt++) {
        #pragma unroll
        for (int nt = 0; nt < 4; nt++) {
            const int m0 = rowBase + warpM * 64 + mt * 16 + (lid >> 2);
            const int cLoc = warpN * 32 + nt * 8 + 2 * (lid & 3);
            const float b0 = bsm[cLoc], b1 = bsm[cLoc + 1];
            const float mz = (m0 & 1) ? mwz1 : mwz0;
            float2 o0, o1;
            o0.x = fmaxf(mz * fmaxf(acc[mt][nt][0] + b0, 0.f), 0.f);
            o0.y = fmaxf(mz * fmaxf(acc[mt][nt][1] + b1, 0.f), 0.f);
            o1.x = fmaxf(mz * fmaxf(acc[mt][nt][2] + b0, 0.f), 0.f);
            o1.y = fmaxf(mz * fmaxf(acc[mt][nt][3] + b1, 0.f), 0.f);
            float* p0 = out + (size_t)m0 * DIM + colBase + cLoc;
            *(float2*)p0 = o0;
            *(float2*)(p0 + (size_t)8 * DIM) = o1;
        }
    }
}

// ---------------- launch ----------------
extern "C" void kernel_launch(void* const* d_in, const int* in_sizes, int n_in,
                              void* d_out, int out_size) {
    const float* x   = (const float*)d_in[0];
    const int*   ids = (const int*)  d_in[1];
    const float* mw  = (const float*)d_in[2];
    const float* emb = (const float*)d_in[3];
    const float* Wt  = (const float*)d_in[4];
    const float* bt  = (const float*)d_in[5];
    const float* Wrc = (const float*)d_in[6];
    const float* brc = (const float*)d_in[7];

    cudaFuncSetAttribute(redaf_mma, cudaFuncAttributeMaxDynamicSharedMemorySize,
                         SMEM_TOTAL);

    zeta_kernel<<<1, 256>>>(Wrc, brc);
    prep_x_kernel<<<NROWS, 512>>>(x, ids, emb);
    prep_w_kernel<<<DIM, 512>>>(Wt);

    dim3 grid(DIM / BN, NROWS / BM);   // (16, 64)
    redaf_mma<<<grid, 256, SMEM_TOTAL>>>(mw, bt, (float*)d_out);
}

// round 6
// speedup vs baseline: 7.8422x; 1.0086x over previous
#include <cuda_runtime.h>
#include <cuda_fp16.h>
#include <cstdint>

#define REL_CONTEXT 0.2f

// ---------------- problem dims (fixed) ----------------
#define NROWS 8192
#define DIM   2048
#define BM    128
#define BN    128
#define BK    64
#define NCH   (DIM / BK)       // 32
#define NSTAGE 3

// ---------------- scratch (chunk-major, pre-swizzled fp16) ----------------
__device__ __align__(128) __half g_Ah[(size_t)NROWS * DIM];
__device__ __align__(128) __half g_Wh[(size_t)DIM * DIM];
__device__ float g_zeta;

// ---------------- PTX helpers (base-target only) ----------------
__device__ __forceinline__ uint32_t smem_to_u32(const void* p) {
    uint32_t a;
    asm("{ .reg .u64 t; cvta.to.shared.u64 t, %1; cvt.u32.u64 %0, t; }"
        : "=r"(a) : "l"(p));
    return a;
}
#define MBARRIER_INIT(addr, cnt) \
    asm volatile("mbarrier.init.shared.b64 [%0], %1;" :: "r"((uint32_t)(addr)), "r"((uint32_t)(cnt)) : "memory")
#define MBARRIER_ARRIVE(addr) \
    asm volatile("mbarrier.arrive.shared.b64 _, [%0];" :: "r"((uint32_t)(addr)) : "memory")
#define MBARRIER_EXPECT_TX(addr, bytes) \
    asm volatile("mbarrier.arrive.expect_tx.shared.b64 _, [%0], %1;" \
                 :: "r"((uint32_t)(addr)), "r"((uint32_t)(bytes)) : "memory")
#define MBARRIER_WAIT_PARITY(addr, par) do { \
    uint32_t _m = (uint32_t)(addr); uint32_t _p = (uint32_t)(par); uint32_t _d; \
    asm volatile("{\n\t.reg .pred p;\n\t" \
        "mbarrier.try_wait.parity.acquire.cta.shared::cta.b64 p, [%1], %2;\n\t" \
        "selp.b32 %0, 1, 0, p;\n\t}" : "=r"(_d) : "r"(_m), "r"(_p) : "memory"); \
    if (!_d) { \
        asm volatile("{\n\t.reg .pred P1;\n\t" \
            "WL_%=:\n\t" \
            "mbarrier.try_wait.parity.acquire.cta.shared::cta.b64 P1, [%0], %1, 0x989680;\n\t" \
            "@P1 bra.uni WD_%=;\n\tbra.uni WL_%=;\n\tWD_%=:\n\t}" \
            :: "r"(_m), "r"(_p) : "memory"); \
    } } while (0)
#define BULK_G2S(dst, src, bytes, mbar) \
    asm volatile("cp.async.bulk.shared::cluster.global.mbarrier::complete_tx::bytes " \
                 "[%0], [%1], %2, [%3];" \
                 :: "r"((uint32_t)(dst)), "l"(src), "r"((uint32_t)(bytes)), \
                    "r"((uint32_t)(mbar)) : "memory")
#define LDMATRIX_X4(r0, r1, r2, r3, addr) \
    asm volatile("ldmatrix.sync.aligned.m8n8.x4.shared.b16 {%0,%1,%2,%3}, [%4];" \
                 : "=r"(r0), "=r"(r1), "=r"(r2), "=r"(r3) : "r"(addr))
#define MMA_F16(d, a, b) \
    asm volatile("mma.sync.aligned.m16n8k16.row.col.f32.f16.f16.f32 " \
                 "{%0,%1,%2,%3}, {%4,%5,%6,%7}, {%8,%9}, {%0,%1,%2,%3};" \
                 : "+f"((d)[0]), "+f"((d)[1]), "+f"((d)[2]), "+f"((d)[3]) \
                 : "r"((a)[0]), "r"((a)[1]), "r"((a)[2]), "r"((a)[3]), \
                   "r"((b)[0]), "r"((b)[1]))

// ---------------- smem layout ----------------
#define SM_BAR   0                    // full[s] at 16*s, empty[s] at 16*s+8
#define SM_BIAS  128                  // 128 floats
#define SM_TILES 1024
#define T_AH     0
#define T_BH     16384
#define STAGE_BYTES 32768             // 2 x 16KB
#define SMEM_TOTAL (SM_TILES + NSTAGE * STAGE_BYTES)   // 99328 (2 CTAs/SM)

// chunk-major, swizzled byte offset for (row, k0): 4 consecutive halves (8B)
__device__ __forceinline__ size_t scratch_off(int nTotRows, int row, int k0) {
    const int chunk = k0 >> 6;
    const int kc = k0 & 63;
    const int ci = kc >> 3;
    const int h8 = (kc >> 2) & 1;
    return ((size_t)chunk * nTotRows + row) * 128 + ((ci ^ (row & 7)) << 4) + h8 * 8;
}

__device__ __forceinline__ uint2 pack_h4(const float v[4]) {
    uint16_t h[4];
    #pragma unroll
    for (int i = 0; i < 4; i++) {
        __half hv = __float2half_rn(v[i]);
        h[i] = *(uint16_t*)&hv;
    }
    return make_uint2((uint32_t)h[0] | ((uint32_t)h[1] << 16),
                      (uint32_t)h[2] | ((uint32_t)h[3] << 16));
}

// ---------------- single merged prep kernel ----------------
// blocks [0, NROWS)           : convert x+emb row -> g_Ah
// blocks [NROWS, NROWS+DIM)   : convert Wt row    -> g_Wh
// block  NROWS+DIM            : zeta
__global__ void prep_all(const float* __restrict__ x,
                         const int* __restrict__ ids,
                         const float* __restrict__ emb,
                         const float* __restrict__ Wt,
                         const float* __restrict__ Wrc,
                         const float* __restrict__ brc) {
    const int b = blockIdx.x;
    const int c4 = threadIdx.x;           // 512 threads, 4 floats each
    if (b < NROWS) {
        const int row = b;
        const int id = ids[row];
        float4 xv = ((const float4*)(x + (size_t)row * DIM))[c4];
        float4 ev = ((const float4*)(emb + (size_t)id * DIM))[c4];
        float v[4] = {xv.x + ev.x, xv.y + ev.y, xv.z + ev.z, xv.w + ev.w};
        *(uint2*)((char*)g_Ah + scratch_off(NROWS, row, c4 * 4)) = pack_h4(v);
    } else if (b < NROWS + DIM) {
        const int row = b - NROWS;
        float4 wv = ((const float4*)(Wt + (size_t)row * DIM))[c4];
        float v[4] = {wv.x, wv.y, wv.z, wv.w};
        *(uint2*)((char*)g_Wh + scratch_off(DIM, row, c4 * 4)) = pack_h4(v);
    } else {
        __shared__ float red[32];
        float s = 0.f;
        for (int i = c4; i < DIM; i += 512) s += Wrc[i];
        #pragma unroll
        for (int o = 16; o > 0; o >>= 1) s += __shfl_down_sync(0xffffffffu, s, o);
        if ((c4 & 31) == 0) red[c4 >> 5] = s;
        __syncthreads();
        if (c4 < 32) {
            float v = (c4 < 16) ? red[c4] : 0.f;
            #pragma unroll
            for (int o = 8; o > 0; o >>= 1) v += __shfl_down_sync(0xffffffffu, v, o);
            if (c4 == 0)
                g_zeta = 1.f / (1.f + expf(-(REL_CONTEXT * v + brc[0])));
        }
    }
}

// ---------------- main MMA kernel ----------------
__global__ __launch_bounds__(256, 2)
void redaf_mma(const float* __restrict__ mw,
               const float* __restrict__ bt,
               float* __restrict__ out) {
    extern __shared__ char smem[];
    const uint32_t sb = smem_to_u32(smem);
    const int tid = threadIdx.x;
    const int wid = tid >> 5;
    const int lid = tid & 31;

    const int colBase = blockIdx.x * BN;
    const int rowBase = blockIdx.y * BM;

    if (tid == 0) {
        #pragma unroll
        for (int s = 0; s < NSTAGE; s++) {
            MBARRIER_INIT(sb + SM_BAR + 16 * s, 1);        // full: expect_tx
            MBARRIER_INIT(sb + SM_BAR + 16 * s + 8, 8);    // empty: 8 warps
        }
    }
    if (tid < BN) ((float*)(smem + SM_BIAS))[tid] = bt[colBase + tid];
    __syncthreads();

    // ---- producer: 2 bulk copies of 16KB per chunk ----
    auto produce = [&](int c) {
        const int s = c % NSTAGE;
        const uint32_t stB = sb + SM_TILES + s * STAGE_BYTES;
        const uint32_t fb = sb + SM_BAR + 16 * s;
        MBARRIER_EXPECT_TX(fb, STAGE_BYTES);
        BULK_G2S(stB + T_AH,
                 (const char*)g_Ah + ((size_t)c * NROWS + rowBase) * 128, 16384, fb);
        BULK_G2S(stB + T_BH,
                 (const char*)g_Wh + ((size_t)c * DIM + colBase) * 128, 16384, fb);
    };

    // prefill stages 0,1 (chunk 2 produced inside iteration 0)
    if (lid == 0 && wid < NSTAGE - 1) produce(wid);

    // ---- per-lane ldmatrix address pieces ----
    const int warpM = wid & 1;
    const int warpN = wid >> 1;
    const int aRowL = warpM * 64 + (lid & 15);
    const int aKhalf = lid >> 4;
    const int bRowL = warpN * 32 + (lid & 7) + ((lid >> 4) & 1) * 8;
    const int bKhalf = (lid >> 3) & 1;

    float acc[4][4][4];
    #pragma unroll
    for (int i = 0; i < 4; i++)
        #pragma unroll
        for (int j = 0; j < 4; j++)
            #pragma unroll
            for (int k = 0; k < 4; k++) acc[i][j][k] = 0.f;

    #pragma unroll 1
    for (int c = 0; c < NCH; c++) {
        const int s = c % NSTAGE;
        const uint32_t par = (c / NSTAGE) & 1;
        const uint32_t fullB = sb + SM_BAR + 16 * s;
        const uint32_t emptyB = fullB + 8;
        MBARRIER_WAIT_PARITY(fullB, par);

        const uint32_t stBase = sb + SM_TILES + s * STAGE_BYTES;
        #pragma unroll
        for (int ks = 0; ks < BK / 16; ks++) {
            uint32_t ah[4][4], bh[4][2];
            #pragma unroll
            for (int mt = 0; mt < 4; mt++) {
                const int row = aRowL + mt * 16;
                const int ch = 2 * ks + aKhalf;
                const uint32_t off = row * 128 + ((ch ^ (row & 7)) << 4);
                LDMATRIX_X4(ah[mt][0], ah[mt][1], ah[mt][2], ah[mt][3],
                            stBase + T_AH + off);
            }
            #pragma unroll
            for (int p = 0; p < 2; p++) {
                const int row = bRowL + p * 16;
                const int ch = 2 * ks + bKhalf;
                const uint32_t off = row * 128 + ((ch ^ (row & 7)) << 4);
                LDMATRIX_X4(bh[2 * p][0], bh[2 * p][1], bh[2 * p + 1][0], bh[2 * p + 1][1],
                            stBase + T_BH + off);
            }
            #pragma unroll
            for (int mt = 0; mt < 4; mt++)
                #pragma unroll
                for (int nt = 0; nt < 4; nt++) MMA_F16(acc[mt][nt], ah[mt], bh[nt]);
        }

        if (lid == 0) {
            MBARRIER_ARRIVE(emptyB);                  // this warp done reading chunk c
            // produce chunk c+2 into stage t=(c+2)%3: its previous readers were
            // chunk c-1's consumers, who arrived at the END of iteration c-1 —
            // one full chunk of slack instead of blocking on current stragglers.
            const int t = (c + 2) % NSTAGE;
            if (wid == t && c + 2 < NCH) {
                if (c + 2 >= NSTAGE) {                // stage t has prior readers
                    MBARRIER_WAIT_PARITY(sb + SM_BAR + 16 * t + 8,
                                         (uint32_t)(((c - 1) / NSTAGE) & 1));
                }
                produce(c + 2);
            }
        }
    }

    // ---- epilogue: bias -> relu -> mw*zeta -> relu ----
    const float zeta = g_zeta;
    const float mwz0 = mw[0] * zeta;
    const float mwz1 = mw[1] * zeta;
    const float* bsm = (const float*)(smem + SM_BIAS);

    #pragma unroll
    for (int mt = 0; mt < 4; mt++) {
        #pragma unroll
        for (int nt = 0; nt < 4; nt++) {
            const int m0 = rowBase + warpM * 64 + mt * 16 + (lid >> 2);
            const int cLoc = warpN * 32 + nt * 8 + 2 * (lid & 3);
            const float b0 = bsm[cLoc], b1 = bsm[cLoc + 1];
            const float mz = (m0 & 1) ? mwz1 : mwz0;
            float2 o0, o1;
            o0.x = fmaxf(mz * fmaxf(acc[mt][nt][0] + b0, 0.f), 0.f);
            o0.y = fmaxf(mz * fmaxf(acc[mt][nt][1] + b1, 0.f), 0.f);
            o1.x = fmaxf(mz * fmaxf(acc[mt][nt][2] + b0, 0.f), 0.f);
            o1.y = fmaxf(mz * fmaxf(acc[mt][nt][3] + b1, 0.f), 0.f);
            float* p0 = out + (size_t)m0 * DIM + colBase + cLoc;
            *(float2*)p0 = o0;
            *(float2*)(p0 + (size_t)8 * DIM) = o1;
        }
    }
}

// ---------------- launch ----------------
extern "C" void kernel_launch(void* const* d_in, const int* in_sizes, int n_in,
                              void* d_out, int out_size) {
    const float* x   = (const float*)d_in[0];
    const int*   ids = (const int*)  d_in[1];
    const float* mw  = (const float*)d_in[2];
    const float* emb = (const float*)d_in[3];
    const float* Wt  = (const float*)d_in[4];
    const float* bt  = (const float*)d_in[5];
    const float* Wrc = (const float*)d_in[6];
    const float* brc = (const float*)d_in[7];

    cudaFuncSetAttribute(redaf_mma, cudaFuncAttributeMaxDynamicSharedMemorySize,
                         SMEM_TOTAL);

    prep_all<<<NROWS + DIM + 1, 512>>>(x, ids, emb, Wt, Wrc, brc);

    dim3 grid(DIM / BN, NROWS / BM);   // (16, 64)
    redaf_mma<<<grid, 256, SMEM_TOTAL>>>(mw, bt, (float*)d_out);
}